// round 2
// baseline (speedup 1.0000x reference)
#include <cuda_runtime.h>
#include <cuda_bf16.h>
#include <math.h>

// Problem shape (fixed)
#define B 8
#define Q 1024
#define KDIM 4096
#define H 512

// d_out layout: [ out (B*Q*H) | attn (B*Q*K) ]
#define OUT_ELEMS (B * Q * H)

// Scratch for mix = attn @ context : [B, Q, H] fp32 (16 MB)
__device__ float g_mix[(size_t)B * Q * H];

// ---------------------------------------------------------------------------
// Kernel 1: scores[b,q,k] = sum_h output[b,q,h]*context[b,k,h]; mask -> -inf
// Tiled 64x64x16 NT SGEMM. Grid (K/64, Q/64, B), block 256 threads (4x4/thread)
// ---------------------------------------------------------------------------
__global__ __launch_bounds__(256) void scores_kernel(
    const float* __restrict__ outp, const float* __restrict__ ctx,
    const int* __restrict__ mask, float* __restrict__ logits)
{
    const int b  = blockIdx.z;
    const int m0 = blockIdx.y * 64;   // Q dim
    const int n0 = blockIdx.x * 64;   // K dim
    const float* A = outp + (size_t)b * Q * H;     // [Q, H] row-major
    const float* Bm = ctx + (size_t)b * KDIM * H;  // [K, H] row-major

    __shared__ float As[16][64];
    __shared__ float Bs[16][64];

    const int t  = threadIdx.x;
    const int tx = t & 15;    // n micro
    const int ty = t >> 4;    // m micro
    const int lr = t >> 2;        // 0..63 tile row for loads
    const int lc = (t & 3) * 4;   // 0,4,8,12 k-offset for loads

    float acc[4][4] = {};

    for (int k0 = 0; k0 < H; k0 += 16) {
        float4 a4 = *(const float4*)(A  + (size_t)(m0 + lr) * H + k0 + lc);
        float4 b4 = *(const float4*)(Bm + (size_t)(n0 + lr) * H + k0 + lc);
        As[lc + 0][lr] = a4.x; As[lc + 1][lr] = a4.y; As[lc + 2][lr] = a4.z; As[lc + 3][lr] = a4.w;
        Bs[lc + 0][lr] = b4.x; Bs[lc + 1][lr] = b4.y; Bs[lc + 2][lr] = b4.z; Bs[lc + 3][lr] = b4.w;
        __syncthreads();
        #pragma unroll
        for (int kk = 0; kk < 16; kk++) {
            float a[4], bb[4];
            #pragma unroll
            for (int i = 0; i < 4; i++) a[i]  = As[kk][ty * 4 + i];
            #pragma unroll
            for (int j = 0; j < 4; j++) bb[j] = Bs[kk][tx * 4 + j];
            #pragma unroll
            for (int i = 0; i < 4; i++)
                #pragma unroll
                for (int j = 0; j < 4; j++)
                    acc[i][j] = fmaf(a[i], bb[j], acc[i][j]);
        }
        __syncthreads();
    }

    const int* Mb = mask + (size_t)b * Q * KDIM;
    float* Cb = logits + (size_t)b * Q * KDIM;
    #pragma unroll
    for (int i = 0; i < 4; i++) {
        const int m = m0 + ty * 4 + i;
        #pragma unroll
        for (int j = 0; j < 4; j++) {
            const int n = n0 + tx * 4 + j;
            float v = acc[i][j];
            if (Mb[(size_t)m * KDIM + n] != 0) v = -INFINITY;
            Cb[(size_t)m * KDIM + n] = v;
        }
    }
}

// ---------------------------------------------------------------------------
// Kernel 2: in-place softmax over K for each (b,q) row. One CTA per row.
// ---------------------------------------------------------------------------
__global__ __launch_bounds__(256) void softmax_kernel(float* __restrict__ attn)
{
    __shared__ float buf[KDIM];
    __shared__ float red[256];
    const size_t row = blockIdx.x;           // b*Q + q
    float* p = attn + row * KDIM;
    const int t = threadIdx.x;

    float lmax = -INFINITY;
    #pragma unroll 4
    for (int i = t; i < KDIM; i += 256) {
        float v = p[i];
        buf[i] = v;
        lmax = fmaxf(lmax, v);
    }
    red[t] = lmax; __syncthreads();
    for (int s = 128; s > 0; s >>= 1) {
        if (t < s) red[t] = fmaxf(red[t], red[t + s]);
        __syncthreads();
    }
    const float mx = red[0];
    __syncthreads();

    float lsum = 0.f;
    #pragma unroll 4
    for (int i = t; i < KDIM; i += 256) {
        float e = __expf(buf[i] - mx);   // exp(-inf)=0 for masked entries
        buf[i] = e;
        lsum += e;
    }
    red[t] = lsum; __syncthreads();
    for (int s = 128; s > 0; s >>= 1) {
        if (t < s) red[t] += red[t + s];
        __syncthreads();
    }
    const float inv = 1.f / red[0];
    #pragma unroll 4
    for (int i = t; i < KDIM; i += 256) p[i] = buf[i] * inv;
}

// ---------------------------------------------------------------------------
// Kernel 3: mix[b,q,h] = sum_k attn[b,q,k]*context[b,k,h]  (NN SGEMM, Kd=4096)
// ---------------------------------------------------------------------------
__global__ __launch_bounds__(256) void mix_kernel(
    const float* __restrict__ attn, const float* __restrict__ ctx,
    float* __restrict__ mix)
{
    const int b  = blockIdx.z;
    const int m0 = blockIdx.y * 64;   // Q dim
    const int n0 = blockIdx.x * 64;   // H dim
    const float* A  = attn + (size_t)b * Q * KDIM;   // [Q, K]
    const float* Bm = ctx  + (size_t)b * KDIM * H;   // [K, H]

    __shared__ float As[16][64];
    __shared__ float Bs[16][64];

    const int t  = threadIdx.x;
    const int tx = t & 15;
    const int ty = t >> 4;
    const int lr = t >> 2;         // A: tile row 0..63
    const int lc = (t & 3) * 4;    // A: k offset
    const int br = t >> 4;         // B: k row 0..15
    const int bc = (t & 15) * 4;   // B: n offset

    float acc[4][4] = {};

    for (int k0 = 0; k0 < KDIM; k0 += 16) {
        float4 a4 = *(const float4*)(A  + (size_t)(m0 + lr) * KDIM + k0 + lc);
        float4 b4 = *(const float4*)(Bm + (size_t)(k0 + br) * H + n0 + bc);
        As[lc + 0][lr] = a4.x; As[lc + 1][lr] = a4.y; As[lc + 2][lr] = a4.z; As[lc + 3][lr] = a4.w;
        Bs[br][bc + 0] = b4.x; Bs[br][bc + 1] = b4.y; Bs[br][bc + 2] = b4.z; Bs[br][bc + 3] = b4.w;
        __syncthreads();
        #pragma unroll
        for (int kk = 0; kk < 16; kk++) {
            float a[4], bb[4];
            #pragma unroll
            for (int i = 0; i < 4; i++) a[i]  = As[kk][ty * 4 + i];
            #pragma unroll
            for (int j = 0; j < 4; j++) bb[j] = Bs[kk][tx * 4 + j];
            #pragma unroll
            for (int i = 0; i < 4; i++)
                #pragma unroll
                for (int j = 0; j < 4; j++)
                    acc[i][j] = fmaf(a[i], bb[j], acc[i][j]);
        }
        __syncthreads();
    }

    float* Cb = mix + (size_t)b * Q * H;
    #pragma unroll
    for (int i = 0; i < 4; i++) {
        const int m = m0 + ty * 4 + i;
        #pragma unroll
        for (int j = 0; j < 4; j++) {
            const int n = n0 + tx * 4 + j;
            Cb[(size_t)m * H + n] = acc[i][j];
        }
    }
}

// ---------------------------------------------------------------------------
// Kernel 4: out[b,q,h] = tanh( sum_c combined[b,q,c]*W[h,c] + bias[h] )
// combined[c] = (c < H) ? mix[b,q,c] : output[b,q,c-H].  NT SGEMM, Kd=1024.
// ---------------------------------------------------------------------------
__global__ __launch_bounds__(256) void out_kernel(
    const float* __restrict__ mix, const float* __restrict__ outp,
    const float* __restrict__ W, const float* __restrict__ bias,
    float* __restrict__ out)
{
    const int b  = blockIdx.z;
    const int m0 = blockIdx.y * 64;   // Q dim
    const int n0 = blockIdx.x * 64;   // H dim
    const float* Mx = mix  + (size_t)b * Q * H;
    const float* Op = outp + (size_t)b * Q * H;

    __shared__ float As[16][64];
    __shared__ float Bs[16][64];

    const int t  = threadIdx.x;
    const int tx = t & 15;
    const int ty = t >> 4;
    const int lr = t >> 2;
    const int lc = (t & 3) * 4;

    float acc[4][4] = {};

    for (int k0 = 0; k0 < 2 * H; k0 += 16) {
        // A: virtual concat [mix | output], each half H wide
        const float* Ahalf = (k0 < H) ? Mx : Op;
        const int kk0 = (k0 < H) ? k0 : (k0 - H);
        float4 a4 = *(const float4*)(Ahalf + (size_t)(m0 + lr) * H + kk0 + lc);
        // B = W_out [H, 2H] row-major, need W[n, c]
        float4 b4 = *(const float4*)(W + (size_t)(n0 + lr) * (2 * H) + k0 + lc);
        As[lc + 0][lr] = a4.x; As[lc + 1][lr] = a4.y; As[lc + 2][lr] = a4.z; As[lc + 3][lr] = a4.w;
        Bs[lc + 0][lr] = b4.x; Bs[lc + 1][lr] = b4.y; Bs[lc + 2][lr] = b4.z; Bs[lc + 3][lr] = b4.w;
        __syncthreads();
        #pragma unroll
        for (int kk = 0; kk < 16; kk++) {
            float a[4], bb[4];
            #pragma unroll
            for (int i = 0; i < 4; i++) a[i]  = As[kk][ty * 4 + i];
            #pragma unroll
            for (int j = 0; j < 4; j++) bb[j] = Bs[kk][tx * 4 + j];
            #pragma unroll
            for (int i = 0; i < 4; i++)
                #pragma unroll
                for (int j = 0; j < 4; j++)
                    acc[i][j] = fmaf(a[i], bb[j], acc[i][j]);
        }
        __syncthreads();
    }

    float* Cb = out + (size_t)b * Q * H;
    #pragma unroll
    for (int i = 0; i < 4; i++) {
        const int m = m0 + ty * 4 + i;
        #pragma unroll
        for (int j = 0; j < 4; j++) {
            const int n = n0 + tx * 4 + j;
            Cb[(size_t)m * H + n] = tanhf(acc[i][j] + bias[n]);
        }
    }
}

// ---------------------------------------------------------------------------
extern "C" void kernel_launch(void* const* d_in, const int* in_sizes, int n_in,
                              void* d_out, int out_size)
{
    const float* outp = (const float*)d_in[0];   // [B,Q,H]
    const float* ctx  = (const float*)d_in[1];   // [B,K,H]
    const int*   mask = (const int*)d_in[2];     // [B,Q,K] bool -> int32
    const float* W    = (const float*)d_in[3];   // [H,2H]
    const float* bias = (const float*)d_in[4];   // [H]

    float* out_part  = (float*)d_out;              // [B,Q,H]
    float* attn_part = (float*)d_out + OUT_ELEMS;  // [B,Q,K]

    float* mixp;
    cudaGetSymbolAddress((void**)&mixp, g_mix);

    // 1. scores + mask -> attn region (as logits)
    {
        dim3 grid(KDIM / 64, Q / 64, B);
        scores_kernel<<<grid, 256>>>(outp, ctx, mask, attn_part);
    }
    // 2. softmax in-place
    softmax_kernel<<<B * Q, 256>>>(attn_part);
    // 3. mix = attn @ context
    {
        dim3 grid(H / 64, Q / 64, B);
        mix_kernel<<<grid, 256>>>(attn_part, ctx, mixp);
    }
    // 4. out = tanh([mix|output] @ W^T + b)
    {
        dim3 grid(H / 64, Q / 64, B);
        out_kernel<<<grid, 256>>>(mixp, outp, W, bias, out_part);
    }
}

// round 4
// speedup vs baseline: 1.8800x; 1.8800x over previous
#include <cuda_runtime.h>
#include <cuda_bf16.h>
#include <math.h>
#include <stdint.h>

// Problem shape (fixed)
#define BBATCH 8
#define QQ 1024
#define KK 4096
#define HH 512
#define OUT_ELEMS (BBATCH * QQ * HH)

// Scratch
__device__ float g_mix[(size_t)BBATCH * QQ * HH];               // 16 MB
__device__ __nv_bfloat16 g_ctxT_hi[(size_t)BBATCH * HH * KK];   // 32 MB  [b][h][k]
__device__ __nv_bfloat16 g_ctxT_lo[(size_t)BBATCH * HH * KK];   // 32 MB

// ---------------------------------------------------------------------------
// helpers
// ---------------------------------------------------------------------------
__device__ __forceinline__ uint32_t smem_u32(const void* p) {
    uint32_t a;
    asm("{ .reg .u64 t; cvta.to.shared.u64 t, %1; cvt.u32.u64 %0, t; }" : "=r"(a) : "l"(p));
    return a;
}

__device__ __forceinline__ void ldsm4(uint32_t* r, uint32_t addr) {
    asm volatile("ldmatrix.sync.aligned.m8n8.x4.shared.b16 {%0,%1,%2,%3}, [%4];"
                 : "=r"(r[0]), "=r"(r[1]), "=r"(r[2]), "=r"(r[3]) : "r"(addr));
}
__device__ __forceinline__ void ldsm2(uint32_t* r, uint32_t addr) {
    asm volatile("ldmatrix.sync.aligned.m8n8.x2.shared.b16 {%0,%1}, [%2];"
                 : "=r"(r[0]), "=r"(r[1]) : "r"(addr));
}
__device__ __forceinline__ void mma_bf16(float* c, const uint32_t* a, const uint32_t* b) {
    asm volatile(
        "mma.sync.aligned.m16n8k16.row.col.f32.bf16.bf16.f32 "
        "{%0,%1,%2,%3}, {%4,%5,%6,%7}, {%8,%9}, {%0,%1,%2,%3};"
        : "+f"(c[0]), "+f"(c[1]), "+f"(c[2]), "+f"(c[3])
        : "r"(a[0]), "r"(a[1]), "r"(a[2]), "r"(a[3]), "r"(b[0]), "r"(b[1]));
}

// fp32 float4 -> hi/lo bf16 packed
__device__ __forceinline__ void split4(float4 v, uint2& ph, uint2& pl) {
    __nv_bfloat16 h0 = __float2bfloat16_rn(v.x);
    __nv_bfloat16 h1 = __float2bfloat16_rn(v.y);
    __nv_bfloat16 h2 = __float2bfloat16_rn(v.z);
    __nv_bfloat16 h3 = __float2bfloat16_rn(v.w);
    __nv_bfloat16 l0 = __float2bfloat16_rn(v.x - __bfloat162float(h0));
    __nv_bfloat16 l1 = __float2bfloat16_rn(v.y - __bfloat162float(h1));
    __nv_bfloat16 l2 = __float2bfloat16_rn(v.z - __bfloat162float(h2));
    __nv_bfloat16 l3 = __float2bfloat16_rn(v.w - __bfloat162float(h3));
    ph.x = (uint32_t)__bfloat16_as_ushort(h0) | ((uint32_t)__bfloat16_as_ushort(h1) << 16);
    ph.y = (uint32_t)__bfloat16_as_ushort(h2) | ((uint32_t)__bfloat16_as_ushort(h3) << 16);
    pl.x = (uint32_t)__bfloat16_as_ushort(l0) | ((uint32_t)__bfloat16_as_ushort(l1) << 16);
    pl.y = (uint32_t)__bfloat16_as_ushort(l2) | ((uint32_t)__bfloat16_as_ushort(l3) << 16);
}

// SMEM tile: 128 rows x 32 cols bf16, padded stride 40 elements (80 B)
#define TSTRIDE 40

// fp32 source [rows=128 x 32], row stride `stride` floats -> hi/lo smem
__device__ __forceinline__ void conv_tile(const float* __restrict__ src, int stride,
                                          uint16_t* hi, uint16_t* lo, int t) {
    #pragma unroll
    for (int u = 0; u < 4; u++) {
        int i = t + u * 256;          // 0..1023
        int r  = i >> 3;
        int c4 = (i & 7) << 2;
        float4 v = *(const float4*)(src + (size_t)r * stride + c4);
        uint2 ph, pl;
        split4(v, ph, pl);
        *(uint2*)(hi + r * TSTRIDE + c4) = ph;
        *(uint2*)(lo + r * TSTRIDE + c4) = pl;
    }
}

// pre-split bf16 source [128 x 32], row stride `stride` bf16 -> hi/lo smem
__device__ __forceinline__ void copy_tile_bf16(const __nv_bfloat16* __restrict__ sh,
                                               const __nv_bfloat16* __restrict__ sl,
                                               int stride, uint16_t* hi, uint16_t* lo, int t) {
    #pragma unroll
    for (int u = 0; u < 2; u++) {
        int i = t + u * 256;          // 0..511
        int r = i >> 2;
        int c8 = (i & 3) << 3;
        uint4 vh = *(const uint4*)(sh + (size_t)r * stride + c8);
        uint4 vl = *(const uint4*)(sl + (size_t)r * stride + c8);
        *(uint4*)(hi + r * TSTRIDE + c8) = vh;
        *(uint4*)(lo + r * TSTRIDE + c8) = vl;
    }
}

// ---------------------------------------------------------------------------
// Unified bf16x3 NT GEMM: C[m][n] = sum_k A[m][k] * B[n][k]
// MODE 0: scores (+mask->-inf)   1: mix   2: out (+bias, tanh)
// CTA tile 128x128, 256 threads (8 warps: 4 in M x 2 in N), K chunk 32.
// ---------------------------------------------------------------------------
template <int MODE>
__global__ __launch_bounds__(256) void gemm_kernel(
    const float* __restrict__ outp, const float* __restrict__ ctx,
    const int* __restrict__ mask, const float* __restrict__ W,
    const float* __restrict__ bias, float* __restrict__ attn,
    float* __restrict__ mixp, float* __restrict__ outpart,
    const __nv_bfloat16* __restrict__ ctxT_hi, const __nv_bfloat16* __restrict__ ctxT_lo)
{
    __shared__ __align__(16) uint16_t Ah[128 * TSTRIDE];
    __shared__ __align__(16) uint16_t Al[128 * TSTRIDE];
    __shared__ __align__(16) uint16_t Bh[128 * TSTRIDE];
    __shared__ __align__(16) uint16_t Bl[128 * TSTRIDE];

    const int t = threadIdx.x, wid = t >> 5, lid = t & 31;
    const int wx = wid & 1;      // N: 2 x 64
    const int wy = wid >> 1;     // M: 4 x 32
    const int b = blockIdx.z, q0 = blockIdx.y * 128, n0 = blockIdx.x * 128;
    const int KLEN = (MODE == 0) ? HH : (MODE == 1) ? KK : 2 * HH;

    float acc[2][8][4];
    #pragma unroll
    for (int mt = 0; mt < 2; mt++)
        #pragma unroll
        for (int nt = 0; nt < 8; nt++)
            #pragma unroll
            for (int j = 0; j < 4; j++) acc[mt][nt][j] = 0.f;

    const uint32_t sAh = smem_u32(Ah), sAl = smem_u32(Al);
    const uint32_t sBh = smem_u32(Bh), sBl = smem_u32(Bl);
    const int lane16 = lid & 15;

    for (int k0 = 0; k0 < KLEN; k0 += 32) {
        // ---- stage A [128 x 32] ----
        if (MODE == 0) {
            conv_tile(outp + ((size_t)(b * QQ + q0)) * HH + k0, HH, Ah, Al, t);
        } else if (MODE == 1) {
            conv_tile(attn + ((size_t)(b * QQ + q0)) * KK + k0, KK, Ah, Al, t);
        } else {
            const float* src = (k0 < HH)
                ? (mixp + ((size_t)(b * QQ + q0)) * HH + k0)
                : (outp + ((size_t)(b * QQ + q0)) * HH + (k0 - HH));
            conv_tile(src, HH, Ah, Al, t);
        }
        // ---- stage B [128 x 32] ----
        if (MODE == 0) {
            conv_tile(ctx + ((size_t)(b * KK + n0)) * HH + k0, HH, Bh, Bl, t);
        } else if (MODE == 1) {
            copy_tile_bf16(ctxT_hi + ((size_t)(b * HH + n0)) * KK + k0,
                           ctxT_lo + ((size_t)(b * HH + n0)) * KK + k0, KK, Bh, Bl, t);
        } else {
            conv_tile(W + (size_t)n0 * (2 * HH) + k0, 2 * HH, Bh, Bl, t);
        }
        __syncthreads();

        // ---- compute: 2 k-tiles of 16 ----
        #pragma unroll
        for (int kt = 0; kt < 2; kt++) {
            uint32_t afh[2][4], afl[2][4];
            #pragma unroll
            for (int mt = 0; mt < 2; mt++) {
                uint32_t off = (uint32_t)((wy * 32 + mt * 16 + lane16) * (TSTRIDE * 2)
                                          + kt * 32 + ((lid >> 4) << 4));
                ldsm4(afh[mt], sAh + off);
                ldsm4(afl[mt], sAl + off);
            }
            #pragma unroll
            for (int nt = 0; nt < 8; nt++) {
                uint32_t boff = (uint32_t)((wx * 64 + nt * 8 + (lane16 & 7)) * (TSTRIDE * 2)
                                           + kt * 32 + (((lane16 >> 3) & 1) << 4));
                uint32_t bfh[2], bfl[2];
                ldsm2(bfh, sBh + boff);
                ldsm2(bfl, sBl + boff);
                #pragma unroll
                for (int mt = 0; mt < 2; mt++) {
                    mma_bf16(acc[mt][nt], afh[mt], bfh);
                    mma_bf16(acc[mt][nt], afh[mt], bfl);
                    mma_bf16(acc[mt][nt], afl[mt], bfh);
                }
            }
        }
        __syncthreads();
    }

    // ---- epilogue ----
    const int rq = lid >> 2;          // 0..7
    const int cq = (lid & 3) * 2;     // 0,2,4,6
    #pragma unroll
    for (int mt = 0; mt < 2; mt++) {
        #pragma unroll
        for (int nt = 0; nt < 8; nt++) {
            const int col = n0 + wx * 64 + nt * 8 + cq;
            #pragma unroll
            for (int half = 0; half < 2; half++) {
                const int row = q0 + wy * 32 + mt * 16 + rq + half * 8;
                float v0 = acc[mt][nt][half * 2 + 0];
                float v1 = acc[mt][nt][half * 2 + 1];
                if (MODE == 0) {
                    const size_t o = ((size_t)(b * QQ + row)) * KK + col;
                    int2 mk = *(const int2*)(mask + o);
                    float2 w2;
                    w2.x = mk.x ? -INFINITY : v0;
                    w2.y = mk.y ? -INFINITY : v1;
                    *(float2*)(attn + o) = w2;
                } else if (MODE == 1) {
                    const size_t o = ((size_t)(b * QQ + row)) * HH + col;
                    *(float2*)(mixp + o) = make_float2(v0, v1);
                } else {
                    const size_t o = ((size_t)(b * QQ + row)) * HH + col;
                    float2 bi = *(const float2*)(bias + col);
                    *(float2*)(outpart + o) = make_float2(tanhf(v0 + bi.x), tanhf(v1 + bi.y));
                }
            }
        }
    }
}

// ---------------------------------------------------------------------------
// Transpose + split: ctx[b][k][h] (fp32) -> ctxT_hi/lo[b][h][k] (bf16)
// ---------------------------------------------------------------------------
__global__ __launch_bounds__(256) void transpose_split_kernel(
    const float* __restrict__ ctx, __nv_bfloat16* __restrict__ th,
    __nv_bfloat16* __restrict__ tl)
{
    __shared__ float tile[32][33];
    const int b = blockIdx.z, k0 = blockIdx.x * 32, h0 = blockIdx.y * 32;
    const int tx = threadIdx.x, ty = threadIdx.y;
    const float* src = ctx + ((size_t)(b * KK + k0)) * HH + h0;
    #pragma unroll
    for (int j = ty; j < 32; j += 8) tile[j][tx] = src[(size_t)j * HH + tx];
    __syncthreads();
    #pragma unroll
    for (int j = ty; j < 32; j += 8) {
        float v = tile[tx][j];   // k = k0+tx, h = h0+j
        __nv_bfloat16 bh = __float2bfloat16_rn(v);
        __nv_bfloat16 bl = __float2bfloat16_rn(v - __bfloat162float(bh));
        size_t o = ((size_t)(b * HH + h0 + j)) * KK + k0 + tx;
        th[o] = bh;
        tl[o] = bl;
    }
}

// ---------------------------------------------------------------------------
// Softmax: one CTA per row, register resident (256 thr x 16 floats)
// ---------------------------------------------------------------------------
__global__ __launch_bounds__(256) void softmax_kernel(float* __restrict__ attn)
{
    const size_t row = blockIdx.x;
    float4* p = (float4*)(attn + row * KK);
    const int t = threadIdx.x, wid = t >> 5, lid = t & 31;
    __shared__ float red[8];

    float4 v[4];
    float mx = -INFINITY;
    #pragma unroll
    for (int j = 0; j < 4; j++) {
        v[j] = p[t + j * 256];
        mx = fmaxf(mx, fmaxf(fmaxf(v[j].x, v[j].y), fmaxf(v[j].z, v[j].w)));
    }
    #pragma unroll
    for (int s = 16; s > 0; s >>= 1) mx = fmaxf(mx, __shfl_xor_sync(0xffffffffu, mx, s));
    if (lid == 0) red[wid] = mx;
    __syncthreads();
    float m2 = red[0];
    #pragma unroll
    for (int i = 1; i < 8; i++) m2 = fmaxf(m2, red[i]);
    __syncthreads();

    float sum = 0.f;
    #pragma unroll
    for (int j = 0; j < 4; j++) {
        v[j].x = __expf(v[j].x - m2);
        v[j].y = __expf(v[j].y - m2);
        v[j].z = __expf(v[j].z - m2);
        v[j].w = __expf(v[j].w - m2);
        sum += v[j].x + v[j].y + v[j].z + v[j].w;
    }
    #pragma unroll
    for (int s = 16; s > 0; s >>= 1) sum += __shfl_xor_sync(0xffffffffu, sum, s);
    if (lid == 0) red[wid] = sum;
    __syncthreads();
    float tot = 0.f;
    #pragma unroll
    for (int i = 0; i < 8; i++) tot += red[i];
    const float inv = 1.f / tot;

    #pragma unroll
    for (int j = 0; j < 4; j++) {
        v[j].x *= inv; v[j].y *= inv; v[j].z *= inv; v[j].w *= inv;
        p[t + j * 256] = v[j];
    }
}

// ---------------------------------------------------------------------------
extern "C" void kernel_launch(void* const* d_in, const int* in_sizes, int n_in,
                              void* d_out, int out_size)
{
    const float* outp = (const float*)d_in[0];   // [B,Q,H]
    const float* ctx  = (const float*)d_in[1];   // [B,K,H]
    const int*   mask = (const int*)d_in[2];     // [B,Q,K] (bool->int32)
    const float* W    = (const float*)d_in[3];   // [H,2H]
    const float* bias = (const float*)d_in[4];   // [H]

    float* out_part  = (float*)d_out;
    float* attn_part = (float*)d_out + OUT_ELEMS;

    float* mixp;
    __nv_bfloat16 *th, *tl;
    cudaGetSymbolAddress((void**)&mixp, g_mix);
    cudaGetSymbolAddress((void**)&th, g_ctxT_hi);
    cudaGetSymbolAddress((void**)&tl, g_ctxT_lo);

    // ctx transpose + split (for mix's B operand)
    {
        dim3 grid(KK / 32, HH / 32, BBATCH);
        transpose_split_kernel<<<grid, dim3(32, 8)>>>(ctx, th, tl);
    }
    // scores (+mask) -> attn region
    {
        dim3 grid(KK / 128, QQ / 128, BBATCH);
        gemm_kernel<0><<<grid, 256>>>(outp, ctx, mask, W, bias,
                                      attn_part, mixp, out_part, th, tl);
    }
    // softmax in place
    softmax_kernel<<<BBATCH * QQ, 256>>>(attn_part);
    // mix = attn @ ctx
    {
        dim3 grid(HH / 128, QQ / 128, BBATCH);
        gemm_kernel<1><<<grid, 256>>>(outp, ctx, mask, W, bias,
                                      attn_part, mixp, out_part, th, tl);
    }
    // out = tanh([mix|output] @ W^T + b)
    {
        dim3 grid(HH / 128, QQ / 128, BBATCH);
        gemm_kernel<2><<<grid, 256>>>(outp, ctx, mask, W, bias,
                                      attn_part, mixp, out_part, th, tl);
    }
}

// round 5
// speedup vs baseline: 2.8426x; 1.5120x over previous
#include <cuda_runtime.h>
#include <cuda_bf16.h>
#include <math.h>
#include <stdint.h>

// Problem shape (fixed)
#define BBATCH 8
#define QQ 1024
#define KK 4096
#define HH 512
#define OUT_ELEMS (BBATCH * QQ * HH)

// Scratch
__device__ float g_mix[(size_t)BBATCH * QQ * HH];               // 16 MB
__device__ __nv_bfloat16 g_ctxT_hi[(size_t)BBATCH * HH * KK];   // 32 MB  [b][h][k]
__device__ __nv_bfloat16 g_ctxT_lo[(size_t)BBATCH * HH * KK];   // 32 MB

// ---------------------------------------------------------------------------
// helpers
// ---------------------------------------------------------------------------
__device__ __forceinline__ uint32_t smem_u32(const void* p) {
    uint32_t a;
    asm("{ .reg .u64 t; cvta.to.shared.u64 t, %1; cvt.u32.u64 %0, t; }" : "=r"(a) : "l"(p));
    return a;
}

__device__ __forceinline__ void ldsm4(uint32_t* r, uint32_t addr) {
    asm volatile("ldmatrix.sync.aligned.m8n8.x4.shared.b16 {%0,%1,%2,%3}, [%4];"
                 : "=r"(r[0]), "=r"(r[1]), "=r"(r[2]), "=r"(r[3]) : "r"(addr));
}
__device__ __forceinline__ void ldsm2(uint32_t* r, uint32_t addr) {
    asm volatile("ldmatrix.sync.aligned.m8n8.x2.shared.b16 {%0,%1}, [%2];"
                 : "=r"(r[0]), "=r"(r[1]) : "r"(addr));
}
__device__ __forceinline__ void mma_bf16(float* c, const uint32_t* a, const uint32_t* b) {
    asm volatile(
        "mma.sync.aligned.m16n8k16.row.col.f32.bf16.bf16.f32 "
        "{%0,%1,%2,%3}, {%4,%5,%6,%7}, {%8,%9}, {%0,%1,%2,%3};"
        : "+f"(c[0]), "+f"(c[1]), "+f"(c[2]), "+f"(c[3])
        : "r"(a[0]), "r"(a[1]), "r"(a[2]), "r"(a[3]), "r"(b[0]), "r"(b[1]));
}

// fp32 float4 -> hi/lo bf16 packed
__device__ __forceinline__ void split4(float4 v, uint2& ph, uint2& pl) {
    __nv_bfloat16 h0 = __float2bfloat16_rn(v.x);
    __nv_bfloat16 h1 = __float2bfloat16_rn(v.y);
    __nv_bfloat16 h2 = __float2bfloat16_rn(v.z);
    __nv_bfloat16 h3 = __float2bfloat16_rn(v.w);
    __nv_bfloat16 l0 = __float2bfloat16_rn(v.x - __bfloat162float(h0));
    __nv_bfloat16 l1 = __float2bfloat16_rn(v.y - __bfloat162float(h1));
    __nv_bfloat16 l2 = __float2bfloat16_rn(v.z - __bfloat162float(h2));
    __nv_bfloat16 l3 = __float2bfloat16_rn(v.w - __bfloat162float(h3));
    ph.x = (uint32_t)__bfloat16_as_ushort(h0) | ((uint32_t)__bfloat16_as_ushort(h1) << 16);
    ph.y = (uint32_t)__bfloat16_as_ushort(h2) | ((uint32_t)__bfloat16_as_ushort(h3) << 16);
    pl.x = (uint32_t)__bfloat16_as_ushort(l0) | ((uint32_t)__bfloat16_as_ushort(l1) << 16);
    pl.y = (uint32_t)__bfloat16_as_ushort(l2) | ((uint32_t)__bfloat16_as_ushort(l3) << 16);
}

// SMEM tile: 128 rows x 32 cols bf16, padded stride 40 elements (80 B)
#define TSTRIDE 40

// ---------------------------------------------------------------------------
// Unified bf16x3 NT GEMM: C[m][n] = sum_k A[m][k] * B[n][k]
// MODE 0: scores (+mask->-inf)   1: mix   2: out (+bias, tanh)
// CTA tile 128x128, 256 threads (8 warps: 4 M x 2 N), K chunk 32.
// Register-prefetch pipeline; 2 CTAs/SM.
// ---------------------------------------------------------------------------
template <int MODE>
__global__ __launch_bounds__(256, 2) void gemm_kernel(
    const float* __restrict__ outp, const float* __restrict__ ctx,
    const int* __restrict__ mask, const float* __restrict__ W,
    const float* __restrict__ bias, float* __restrict__ attn,
    float* __restrict__ mixp, float* __restrict__ outpart,
    const __nv_bfloat16* __restrict__ ctxT_hi, const __nv_bfloat16* __restrict__ ctxT_lo)
{
    __shared__ __align__(16) uint16_t Ah[128 * TSTRIDE];
    __shared__ __align__(16) uint16_t Al[128 * TSTRIDE];
    __shared__ __align__(16) uint16_t Bh[128 * TSTRIDE];
    __shared__ __align__(16) uint16_t Bl[128 * TSTRIDE];

    const int t = threadIdx.x, wid = t >> 5, lid = t & 31;
    const int wx = wid & 1;      // N: 2 x 64
    const int wy = wid >> 1;     // M: 4 x 32
    const int b = blockIdx.z, q0 = blockIdx.y * 128, n0 = blockIdx.x * 128;
    const int KLEN = (MODE == 0) ? HH : (MODE == 1) ? KK : 2 * HH;
    const int NCH = KLEN / 32;

    // precomputed load coordinates (fp32 conv path): 4 x (row, col4)
    const int cr[4] = { (t + 0) >> 3, (t + 256) >> 3, (t + 512) >> 3, (t + 768) >> 3 };
    const int cc    = (t & 7) << 2;
    // bf16 copy path (MODE 1 B): 2 x (row, col8)
    const int br2[2] = { t >> 2, (t + 256) >> 2 };
    const int bc2    = (t & 3) << 3;

    float acc[2][8][4];
    #pragma unroll
    for (int mt = 0; mt < 2; mt++)
        #pragma unroll
        for (int nt = 0; nt < 8; nt++)
            #pragma unroll
            for (int j = 0; j < 4; j++) acc[mt][nt][j] = 0.f;

    const uint32_t sAh = smem_u32(Ah), sAl = smem_u32(Al);
    const uint32_t sBh = smem_u32(Bh), sBl = smem_u32(Bl);
    const int lane16 = lid & 15;

    // prefetch registers
    float4 fa[4];
    float4 fb[4];
    uint4  vh[2], vl[2];

    // ---- chunk load into registers ----
    auto load_chunk = [&](int ch) {
        const int k0 = ch * 32;
        // A
        const float* asrc;
        if (MODE == 0)      asrc = outp + ((size_t)(b * QQ + q0)) * HH + k0;
        else if (MODE == 1) asrc = attn + ((size_t)(b * QQ + q0)) * KK + k0;
        else asrc = (k0 < HH) ? (mixp + ((size_t)(b * QQ + q0)) * HH + k0)
                              : (outp + ((size_t)(b * QQ + q0)) * HH + (k0 - HH));
        const int astr = (MODE == 1) ? KK : HH;
        #pragma unroll
        for (int u = 0; u < 4; u++)
            fa[u] = *(const float4*)(asrc + (size_t)cr[u] * astr + cc);
        // B
        if (MODE == 1) {
            const __nv_bfloat16* sh = ctxT_hi + ((size_t)(b * HH + n0)) * KK + k0;
            const __nv_bfloat16* sl = ctxT_lo + ((size_t)(b * HH + n0)) * KK + k0;
            #pragma unroll
            for (int u = 0; u < 2; u++) {
                vh[u] = *(const uint4*)(sh + (size_t)br2[u] * KK + bc2);
                vl[u] = *(const uint4*)(sl + (size_t)br2[u] * KK + bc2);
            }
        } else {
            const float* bsrc = (MODE == 0)
                ? (ctx + ((size_t)(b * KK + n0)) * HH + k0)
                : (W + (size_t)n0 * (2 * HH) + k0);
            const int bstr = (MODE == 0) ? HH : 2 * HH;
            #pragma unroll
            for (int u = 0; u < 4; u++)
                fb[u] = *(const float4*)(bsrc + (size_t)cr[u] * bstr + cc);
        }
    };

    // ---- chunk store registers -> smem (with split) ----
    auto store_chunk = [&]() {
        #pragma unroll
        for (int u = 0; u < 4; u++) {
            uint2 ph, pl;
            split4(fa[u], ph, pl);
            *(uint2*)(Ah + cr[u] * TSTRIDE + cc) = ph;
            *(uint2*)(Al + cr[u] * TSTRIDE + cc) = pl;
        }
        if (MODE == 1) {
            #pragma unroll
            for (int u = 0; u < 2; u++) {
                *(uint4*)(Bh + br2[u] * TSTRIDE + bc2) = vh[u];
                *(uint4*)(Bl + br2[u] * TSTRIDE + bc2) = vl[u];
            }
        } else {
            #pragma unroll
            for (int u = 0; u < 4; u++) {
                uint2 ph, pl;
                split4(fb[u], ph, pl);
                *(uint2*)(Bh + cr[u] * TSTRIDE + cc) = ph;
                *(uint2*)(Bl + cr[u] * TSTRIDE + cc) = pl;
            }
        }
    };

    load_chunk(0);
    store_chunk();
    __syncthreads();

    for (int ch = 0; ch < NCH; ch++) {
        if (ch + 1 < NCH) load_chunk(ch + 1);   // gmem loads overlap MMAs below

        #pragma unroll
        for (int kt = 0; kt < 2; kt++) {
            uint32_t afh[2][4], afl[2][4];
            #pragma unroll
            for (int mt = 0; mt < 2; mt++) {
                uint32_t off = (uint32_t)((wy * 32 + mt * 16 + lane16) * (TSTRIDE * 2)
                                          + kt * 32 + ((lid >> 4) << 4));
                ldsm4(afh[mt], sAh + off);
                ldsm4(afl[mt], sAl + off);
            }
            #pragma unroll
            for (int nt = 0; nt < 8; nt++) {
                uint32_t boff = (uint32_t)((wx * 64 + nt * 8 + (lane16 & 7)) * (TSTRIDE * 2)
                                           + kt * 32 + (((lane16 >> 3) & 1) << 4));
                uint32_t bfh[2], bfl[2];
                ldsm2(bfh, sBh + boff);
                ldsm2(bfl, sBl + boff);
                #pragma unroll
                for (int mt = 0; mt < 2; mt++) {
                    mma_bf16(acc[mt][nt], afh[mt], bfh);
                    mma_bf16(acc[mt][nt], afh[mt], bfl);
                    mma_bf16(acc[mt][nt], afl[mt], bfh);
                }
            }
        }
        __syncthreads();
        if (ch + 1 < NCH) {
            store_chunk();
            __syncthreads();
        }
    }

    // ---- epilogue ----
    const int rq = lid >> 2;          // 0..7
    const int cq = (lid & 3) * 2;     // 0,2,4,6
    #pragma unroll
    for (int mt = 0; mt < 2; mt++) {
        #pragma unroll
        for (int nt = 0; nt < 8; nt++) {
            const int col = n0 + wx * 64 + nt * 8 + cq;
            #pragma unroll
            for (int half = 0; half < 2; half++) {
                const int row = q0 + wy * 32 + mt * 16 + rq + half * 8;
                float v0 = acc[mt][nt][half * 2 + 0];
                float v1 = acc[mt][nt][half * 2 + 1];
                if (MODE == 0) {
                    const size_t o = ((size_t)(b * QQ + row)) * KK + col;
                    int2 mk = *(const int2*)(mask + o);
                    float2 w2;
                    w2.x = mk.x ? -INFINITY : v0;
                    w2.y = mk.y ? -INFINITY : v1;
                    *(float2*)(attn + o) = w2;
                } else if (MODE == 1) {
                    const size_t o = ((size_t)(b * QQ + row)) * HH + col;
                    *(float2*)(mixp + o) = make_float2(v0, v1);
                } else {
                    const size_t o = ((size_t)(b * QQ + row)) * HH + col;
                    float2 bi = *(const float2*)(bias + col);
                    *(float2*)(outpart + o) = make_float2(tanhf(v0 + bi.x), tanhf(v1 + bi.y));
                }
            }
        }
    }
}

// ---------------------------------------------------------------------------
// Transpose + split: ctx[b][k][h] (fp32) -> ctxT_hi/lo[b][h][k] (bf16)
// Packed 2-per-thread writes (4B stores).
// ---------------------------------------------------------------------------
__global__ __launch_bounds__(256) void transpose_split_kernel(
    const float* __restrict__ ctx, __nv_bfloat16* __restrict__ th,
    __nv_bfloat16* __restrict__ tl)
{
    __shared__ float tile[32][33];
    const int b = blockIdx.z, k0 = blockIdx.x * 32, h0 = blockIdx.y * 32;
    const int t = threadIdx.x;
    const int tx = t & 31, ty = t >> 5;
    const float* src = ctx + ((size_t)(b * KK + k0)) * HH + h0;
    #pragma unroll
    for (int j = ty; j < 32; j += 8) tile[j][tx] = src[(size_t)j * HH + tx];
    __syncthreads();
    // output: 32 h x 16 k-pairs = 512 uint32 slots; each thread writes 2
    const int h  = t >> 3;         // 0..31
    const int p0 = t & 7;          // 0..7
    #pragma unroll
    for (int s = 0; s < 2; s++) {
        const int p = p0 + s * 8;          // 0..15
        float v0 = tile[2 * p + 0][h];
        float v1 = tile[2 * p + 1][h];
        __nv_bfloat16 h0b = __float2bfloat16_rn(v0);
        __nv_bfloat16 h1b = __float2bfloat16_rn(v1);
        __nv_bfloat16 l0b = __float2bfloat16_rn(v0 - __bfloat162float(h0b));
        __nv_bfloat16 l1b = __float2bfloat16_rn(v1 - __bfloat162float(h1b));
        uint32_t ph = (uint32_t)__bfloat16_as_ushort(h0b) | ((uint32_t)__bfloat16_as_ushort(h1b) << 16);
        uint32_t pl = (uint32_t)__bfloat16_as_ushort(l0b) | ((uint32_t)__bfloat16_as_ushort(l1b) << 16);
        size_t o = ((size_t)(b * HH + h0 + h)) * KK + k0 + 2 * p;
        *(uint32_t*)(th + o) = ph;
        *(uint32_t*)(tl + o) = pl;
    }
}

// ---------------------------------------------------------------------------
// Softmax: one CTA per row, register resident (256 thr x 16 floats)
// ---------------------------------------------------------------------------
__global__ __launch_bounds__(256) void softmax_kernel(float* __restrict__ attn)
{
    const size_t row = blockIdx.x;
    float4* p = (float4*)(attn + row * KK);
    const int t = threadIdx.x, wid = t >> 5, lid = t & 31;
    __shared__ float red[8];

    float4 v[4];
    float mx = -INFINITY;
    #pragma unroll
    for (int j = 0; j < 4; j++) {
        v[j] = p[t + j * 256];
        mx = fmaxf(mx, fmaxf(fmaxf(v[j].x, v[j].y), fmaxf(v[j].z, v[j].w)));
    }
    #pragma unroll
    for (int s = 16; s > 0; s >>= 1) mx = fmaxf(mx, __shfl_xor_sync(0xffffffffu, mx, s));
    if (lid == 0) red[wid] = mx;
    __syncthreads();
    float m2 = red[0];
    #pragma unroll
    for (int i = 1; i < 8; i++) m2 = fmaxf(m2, red[i]);
    __syncthreads();

    float sum = 0.f;
    #pragma unroll
    for (int j = 0; j < 4; j++) {
        v[j].x = __expf(v[j].x - m2);
        v[j].y = __expf(v[j].y - m2);
        v[j].z = __expf(v[j].z - m2);
        v[j].w = __expf(v[j].w - m2);
        sum += v[j].x + v[j].y + v[j].z + v[j].w;
    }
    #pragma unroll
    for (int s = 16; s > 0; s >>= 1) sum += __shfl_xor_sync(0xffffffffu, sum, s);
    if (lid == 0) red[wid] = sum;
    __syncthreads();
    float tot = 0.f;
    #pragma unroll
    for (int i = 0; i < 8; i++) tot += red[i];
    const float inv = 1.f / tot;

    #pragma unroll
    for (int j = 0; j < 4; j++) {
        v[j].x *= inv; v[j].y *= inv; v[j].z *= inv; v[j].w *= inv;
        p[t + j * 256] = v[j];
    }
}

// ---------------------------------------------------------------------------
extern "C" void kernel_launch(void* const* d_in, const int* in_sizes, int n_in,
                              void* d_out, int out_size)
{
    const float* outp = (const float*)d_in[0];   // [B,Q,H]
    const float* ctx  = (const float*)d_in[1];   // [B,K,H]
    const int*   mask = (const int*)d_in[2];     // [B,Q,K] (bool->int32)
    const float* W    = (const float*)d_in[3];   // [H,2H]
    const float* bias = (const float*)d_in[4];   // [H]

    float* out_part  = (float*)d_out;
    float* attn_part = (float*)d_out + OUT_ELEMS;

    float* mixp;
    __nv_bfloat16 *th, *tl;
    cudaGetSymbolAddress((void**)&mixp, g_mix);
    cudaGetSymbolAddress((void**)&th, g_ctxT_hi);
    cudaGetSymbolAddress((void**)&tl, g_ctxT_lo);

    // ctx transpose + split (for mix's B operand)
    {
        dim3 grid(KK / 32, HH / 32, BBATCH);
        transpose_split_kernel<<<grid, 256>>>(ctx, th, tl);
    }
    // scores (+mask) -> attn region
    {
        dim3 grid(KK / 128, QQ / 128, BBATCH);
        gemm_kernel<0><<<grid, 256>>>(outp, ctx, mask, W, bias,
                                      attn_part, mixp, out_part, th, tl);
    }
    // softmax in place
    softmax_kernel<<<BBATCH * QQ, 256>>>(attn_part);
    // mix = attn @ ctx
    {
        dim3 grid(HH / 128, QQ / 128, BBATCH);
        gemm_kernel<1><<<grid, 256>>>(outp, ctx, mask, W, bias,
                                      attn_part, mixp, out_part, th, tl);
    }
    // out = tanh([mix|output] @ W^T + b)
    {
        dim3 grid(HH / 128, QQ / 128, BBATCH);
        gemm_kernel<2><<<grid, 256>>>(outp, ctx, mask, W, bias,
                                      attn_part, mixp, out_part, th, tl);
    }
}